// round 14
// baseline (speedup 1.0000x reference)
#include <cuda_runtime.h>
#include <cuda_fp16.h>
#include <math.h>
#include <stdint.h>

#define R_ 8
#define N_ 4096
#define F_ 256
#define B_ 16384
#define KSPLIT 2
#define KHALF (N_ / KSPLIT)         // 2048

// ---------------- scratch (device globals; no allocs allowed) ----------------
__device__ float g_T1[(size_t)R_ * N_ * F_];            // 32 MB
__device__ float g_T2[(size_t)R_ * KSPLIT * N_ * F_];   // 64 MB (split-K partials)
__device__ float g_H1[(size_t)N_ * F_];                 // 4 MB
__device__ float g_H2[(size_t)N_ * F_];                 // 4 MB
__device__ float g_diag[R_ * F_];
__device__ unsigned g_maxbits;
__device__ float g_bscale, g_binv;
// fp16 planes: B = bscale * T1, transposed to [r][o][k]
__device__ __half g_Bh[(size_t)R_ * F_ * N_];  // 16 MB
__device__ __half g_Bl[(size_t)R_ * F_ * N_];  // 16 MB
// fp16 planes for the small GEMMs
__device__ __half g_Xh[(size_t)N_ * F_], g_Xl[(size_t)N_ * F_];        // features
__device__ __half g_W1h[(size_t)R_ * F_ * F_], g_W1l[(size_t)R_ * F_ * F_];
__device__ __half g_W2h[(size_t)R_ * F_ * F_], g_W2l[(size_t)R_ * F_ * F_];
__device__ __half g_Hh[(size_t)N_ * F_], g_Hl[(size_t)N_ * F_];        // H1 * 2^-4

// ---------------- mma / ldmatrix / cp.async helpers ----------------
__device__ __forceinline__ void mma_f16(float* d, const uint32_t* a, const uint32_t* b) {
    asm volatile(
        "mma.sync.aligned.m16n8k16.row.col.f32.f16.f16.f32 "
        "{%0,%1,%2,%3}, {%4,%5,%6,%7}, {%8,%9}, {%0,%1,%2,%3};"
        : "+f"(d[0]), "+f"(d[1]), "+f"(d[2]), "+f"(d[3])
        : "r"(a[0]), "r"(a[1]), "r"(a[2]), "r"(a[3]), "r"(b[0]), "r"(b[1]));
}
__device__ __forceinline__ void ldm4(uint32_t& r0, uint32_t& r1, uint32_t& r2, uint32_t& r3,
                                     uint32_t addr) {
    asm volatile("ldmatrix.sync.aligned.m8n8.x4.shared.b16 {%0,%1,%2,%3}, [%4];"
                 : "=r"(r0), "=r"(r1), "=r"(r2), "=r"(r3) : "r"(addr));
}
__device__ __forceinline__ void cpasync16(uint32_t dst, const void* src) {
    asm volatile("cp.async.ca.shared.global [%0], [%1], 16;" :: "r"(dst), "l"(src));
}
__device__ __forceinline__ uint32_t smem_u32(const void* p) {
    uint32_t a;
    asm("{ .reg .u64 t; cvta.to.shared.u64 t, %1; cvt.u32.u64 %0, t; }" : "=r"(a) : "l"(p));
    return a;
}
__device__ __forceinline__ void split_h(float x, __half& h, __half& l) {
    h = __float2half_rn(x);
    l = __float2half_rn(x - __half2float(h));
}

// ============================================================================
// generic fp32 -> hi/lo fp16 plane split (8 elements/thread, no scale)
// ============================================================================
__global__ __launch_bounds__(256)
void presplit16_kernel(const float* __restrict__ src,
                       __half* __restrict__ dh, __half* __restrict__ dl)
{
    size_t i = ((size_t)blockIdx.x * 256 + threadIdx.x) * 8;
    float4 v0 = *(const float4*)(src + i);
    float4 v1 = *(const float4*)(src + i + 4);
    float a[8] = {v0.x, v0.y, v0.z, v0.w, v1.x, v1.y, v1.z, v1.w};
    __half h[8], l[8];
#pragma unroll
    for (int j = 0; j < 8; j++) split_h(a[j], h[j], l[j]);
    *(uint4*)(dh + i) = *(uint4*)h;
    *(uint4*)(dl + i) = *(uint4*)l;
}

// ============================================================================
// bsplit B: T1 [r][k][o] fp32 -> Bh/Bl [r][o][k] fp16 (transpose + scale + split)
// ============================================================================
__global__ void bsplitB_kernel(const float* __restrict__ T1)
{
    __shared__ float tile[32][33];
    const int tx = threadIdx.x, ty = threadIdx.y;   // (32, 8)
    const int k0 = blockIdx.x * 32, o0 = blockIdx.y * 32, r = blockIdx.z;
    const float s = g_bscale;

    const float* src = T1 + ((size_t)r * N_ + k0) * F_ + o0;
#pragma unroll
    for (int j = 0; j < 4; j++)
        tile[ty + j * 8][tx] = src[(size_t)(ty + j * 8) * F_ + tx];
    __syncthreads();

#pragma unroll
    for (int j = 0; j < 4; j++) {
        int o = ty + j * 8;
        float x = tile[tx][o] * s;
        __half h, l;
        split_h(x, h, l);
        size_t base = ((size_t)r * F_ + o0 + o) * (size_t)N_ + k0 + tx;
        g_Bh[base] = h;
        g_Bl[base] = l;
    }
}

__global__ void reset_kernel() { g_maxbits = 0u; }
__global__ void finalize_kernel() {
    float mx = __uint_as_float(g_maxbits);
    int ex = 0;
    frexpf(mx, &ex);
    int e = ex > 12 ? ex - 12 : 0;   // scaled max <= 4096
    g_bscale = exp2f((float)(-e));
    g_binv   = exp2f((float)(e));
}

// ============================================================================
// small fp16 MMA GEMM (3-product EFT): T1[r][n][o] = unscale * sum_k Ap[n,k]*Bp[r,o,k]
// K=256 (16 chunks). Same pipeline as the proven R13 big kernel.
// Epilogue: store fp32 + maxabs -> g_maxbits.
// ============================================================================
#define BK 16
#define S_NCH (F_ / BK)             // 16
#define STG_AH 0
#define STG_AL 6144
#define STG_BH 12288
#define STG_BL 18432
#define STG_BYTES 24576
#define SMEM_SMALL (4 * STG_BYTES)  // 98304

__global__ __launch_bounds__(256, 2)
void small_f16_kernel(const __half* __restrict__ Aph, const __half* __restrict__ Apl,
                      const __half* __restrict__ Bph, const __half* __restrict__ Bpl,
                      float* __restrict__ Cout, float unscale)
{
    extern __shared__ __align__(16) char smc[];
    uint32_t sb = smem_u32(smc);

    const int tid = threadIdx.x;
    const int wid = tid >> 5;
    const int lane = tid & 31;
    const int g = lane >> 2;
    const int t = lane & 3;

    const int r  = blockIdx.z;
    const int n0 = blockIdx.y * 128;
    const int o0 = blockIdx.x * 128;
    const int wm = (wid & 1) * 64;
    const int wn = (wid >> 1) * 32;

    const int row = tid >> 1, half = tid & 1;
    const __half* sAh = Aph + (size_t)(n0 + row) * F_ + half * 8;   // shared across r
    const __half* sAl = Apl + (size_t)(n0 + row) * F_ + half * 8;
    const __half* sBh = Bph + ((size_t)(r * F_ + o0 + row)) * F_ + half * 8;
    const __half* sBl = Bpl + ((size_t)(r * F_ + o0 + row)) * F_ + half * 8;
    const uint32_t doff = (uint32_t)(row * 48 + half * 16);

    const uint32_t lma = (uint32_t)((wm + ((lane >> 3) & 1) * 8 + (lane & 7)) * 48
                                    + ((lane >> 4) & 1) * 16);
    const uint32_t lmb = (uint32_t)((wn + ((lane >> 4) & 1) * 8 + (lane & 7)) * 48
                                    + ((lane >> 3) & 1) * 16);

    float acc[4][4][4];
#pragma unroll
    for (int mi = 0; mi < 4; mi++)
#pragma unroll
        for (int ni = 0; ni < 4; ni++)
#pragma unroll
            for (int q = 0; q < 4; q++) acc[mi][ni][q] = 0.f;

    auto issue = [&](int stage, int k0) {
        uint32_t d = sb + stage * STG_BYTES + doff;
        cpasync16(d + STG_AH, sAh + k0);
        cpasync16(d + STG_AL, sAl + k0);
        cpasync16(d + STG_BH, sBh + k0);
        cpasync16(d + STG_BL, sBl + k0);
    };

    auto compute = [&](int stage) {
        uint32_t base = sb + stage * STG_BYTES;
        uint32_t bh[4][2], bl[4][2];
#pragma unroll
        for (int p = 0; p < 2; p++) {
            uint32_t r0, r1, r2, r3;
            ldm4(r0, r1, r2, r3, base + STG_BH + lmb + p * 768);
            bh[2 * p][0] = r0; bh[2 * p][1] = r1;
            bh[2 * p + 1][0] = r2; bh[2 * p + 1][1] = r3;
            ldm4(r0, r1, r2, r3, base + STG_BL + lmb + p * 768);
            bl[2 * p][0] = r0; bl[2 * p][1] = r1;
            bl[2 * p + 1][0] = r2; bl[2 * p + 1][1] = r3;
        }
#pragma unroll
        for (int mi = 0; mi < 4; mi++) {
            uint32_t ah[4], al[4];
            ldm4(ah[0], ah[1], ah[2], ah[3], base + STG_AH + lma + mi * 768);
            ldm4(al[0], al[1], al[2], al[3], base + STG_AL + lma + mi * 768);
#pragma unroll
            for (int ni = 0; ni < 4; ni++) {
                mma_f16(acc[mi][ni], ah, bh[ni]);
                mma_f16(acc[mi][ni], ah, bl[ni]);
                mma_f16(acc[mi][ni], al, bh[ni]);
            }
        }
    };

#pragma unroll
    for (int s = 0; s < 3; s++) {
        issue(s, s * BK);
        asm volatile("cp.async.commit_group;" ::: "memory");
    }
    for (int ch = 0; ch < S_NCH; ch++) {
        asm volatile("cp.async.wait_group 2;" ::: "memory");
        __syncthreads();
        compute(ch & 3);
        int nx = ch + 3;
        if (nx < S_NCH) issue(nx & 3, nx * BK);
        asm volatile("cp.async.commit_group;" ::: "memory");
    }

    // epilogue: unscale, store fp32 T1, maxabs reduction
    float mx = 0.f;
    float* Cop = Cout + (size_t)r * N_ * F_;
#pragma unroll
    for (int mi = 0; mi < 4; mi++) {
#pragma unroll
        for (int ni = 0; ni < 4; ni++) {
            int row0 = n0 + wm + mi * 16 + g;
            int col  = o0 + wn + ni * 8 + t * 2;
            float v0 = acc[mi][ni][0] * unscale, v1 = acc[mi][ni][1] * unscale;
            float v2 = acc[mi][ni][2] * unscale, v3 = acc[mi][ni][3] * unscale;
            *(float2*)(Cop + (size_t)row0 * F_ + col) = make_float2(v0, v1);
            *(float2*)(Cop + (size_t)(row0 + 8) * F_ + col) = make_float2(v2, v3);
            mx = fmaxf(mx, fmaxf(fmaxf(fabsf(v0), fabsf(v1)), fmaxf(fabsf(v2), fabsf(v3))));
        }
    }
#pragma unroll
    for (int o = 16; o; o >>= 1) mx = fmaxf(mx, __shfl_xor_sync(0xffffffffu, mx, o));
    if (lane == 0) atomicMax(&g_maxbits, __float_as_uint(mx));
}

// ============================================================================
// big fp16 MMA GEMM, SPLIT-K x2, in-kernel A conversion (presplitA deleted):
// per chunk: cp.async fp32 A (4-deep) + Bh/Bl; convert A -> single-buffered
// fp16 hi/lo planes (c folded, same arithmetic as old presplitA); barrier;
// ldmatrix + 3-product EFT MMAs (R13-proven block).
// ============================================================================
#define NCH (KHALF / BK)            // 128 chunks per CTA
#define OFF_AF32 0                  // 4 stages x (128 rows x 80 B) = 40960
#define AF32_STG 10240
#define OFF_BH 40960                // 4 stages x 6144
#define OFF_BL 65536                // 4 stages x 6144
#define OFF_AH 90112                // single buffer, 6144
#define OFF_AL 96256                // single buffer, 6144
#define SMEM_BIG 102400

__global__ __launch_bounds__(256, 2)
void big_f16_kernel(const float* __restrict__ Aadj, const float* __restrict__ cvec,
                    float* __restrict__ Cout)
{
    extern __shared__ __align__(16) char smc[];
    uint32_t sb = smem_u32(smc);

    const int tid = threadIdx.x;
    const int wid = tid >> 5;
    const int lane = tid & 31;
    const int g = lane >> 2;
    const int t = lane & 3;

    const int z  = blockIdx.z;          // 0..15
    const int r  = z >> 1;
    const int kh = z & 1;
    const int kbase = kh * KHALF;
    const int n0 = blockIdx.y * 128;
    const int o0 = blockIdx.x * 128;
    const int wm = (wid & 1) * 64;
    const int wn = (wid >> 1) * 32;

    const int row = tid >> 1, half = tid & 1;
    const float cv = __ldg(cvec + r * N_ + n0 + row);
    const float* sA = Aadj + ((size_t)(r * N_ + n0 + row)) * N_ + kbase + half * 8;
    const __half* sBh = g_Bh + ((size_t)(r * F_ + o0 + row)) * N_ + kbase + half * 8;
    const __half* sBl = g_Bl + ((size_t)(r * F_ + o0 + row)) * N_ + kbase + half * 8;

    const uint32_t dA32 = (uint32_t)(row * 80 + half * 32);
    const uint32_t dB   = (uint32_t)(row * 48 + half * 16);

    const uint32_t lma = (uint32_t)((wm + ((lane >> 3) & 1) * 8 + (lane & 7)) * 48
                                    + ((lane >> 4) & 1) * 16);
    const uint32_t lmb = (uint32_t)((wn + ((lane >> 4) & 1) * 8 + (lane & 7)) * 48
                                    + ((lane >> 3) & 1) * 16);

    float acc[4][4][4];
#pragma unroll
    for (int mi = 0; mi < 4; mi++)
#pragma unroll
        for (int ni = 0; ni < 4; ni++)
#pragma unroll
            for (int q = 0; q < 4; q++) acc[mi][ni][q] = 0.f;

    auto issue = [&](int stage, int k0) {
        uint32_t da = sb + OFF_AF32 + stage * AF32_STG + dA32;
        cpasync16(da,      sA + k0);          // 4 floats
        cpasync16(da + 16, sA + k0 + 4);      // 4 floats
        uint32_t db = sb + stage * 6144 + dB;
        cpasync16(db + OFF_BH, sBh + k0);
        cpasync16(db + OFF_BL, sBl + k0);
    };

    // fp32 staging -> c-scaled hi/lo fp16 planes (identical math to old presplitA)
    auto convertA = [&](int stage) {
        const float4* af = (const float4*)(smc + OFF_AF32 + stage * AF32_STG
                                           + row * 80 + half * 32);
        float4 f0 = af[0], f1 = af[1];
        float a[8] = {f0.x * cv, f0.y * cv, f0.z * cv, f0.w * cv,
                      f1.x * cv, f1.y * cv, f1.z * cv, f1.w * cv};
        __half h[8], l[8];
#pragma unroll
        for (int j = 0; j < 8; j++) split_h(a[j], h[j], l[j]);
        *(uint4*)(smc + OFF_AH + row * 48 + half * 16) = *(uint4*)h;
        *(uint4*)(smc + OFF_AL + row * 48 + half * 16) = *(uint4*)l;
    };

    auto compute = [&](int stage) {
        uint32_t bbase = sb + stage * 6144;
        uint32_t bh[4][2], bl[4][2];
#pragma unroll
        for (int p = 0; p < 2; p++) {
            uint32_t r0, r1, r2, r3;
            ldm4(r0, r1, r2, r3, bbase + OFF_BH + lmb + p * 768);
            bh[2 * p][0] = r0; bh[2 * p][1] = r1;
            bh[2 * p + 1][0] = r2; bh[2 * p + 1][1] = r3;
            ldm4(r0, r1, r2, r3, bbase + OFF_BL + lmb + p * 768);
            bl[2 * p][0] = r0; bl[2 * p][1] = r1;
            bl[2 * p + 1][0] = r2; bl[2 * p + 1][1] = r3;
        }
#pragma unroll
        for (int mi = 0; mi < 4; mi++) {
            uint32_t ah[4], al[4];
            ldm4(ah[0], ah[1], ah[2], ah[3], sb + OFF_AH + lma + mi * 768);
            ldm4(al[0], al[1], al[2], al[3], sb + OFF_AL + lma + mi * 768);
#pragma unroll
            for (int ni = 0; ni < 4; ni++) {
                mma_f16(acc[mi][ni], ah, bh[ni]);   // hi*hi
                mma_f16(acc[mi][ni], ah, bl[ni]);   // hi*lo
                mma_f16(acc[mi][ni], al, bh[ni]);   // lo*hi
            }
        }
    };

#pragma unroll
    for (int s = 0; s < 3; s++) {
        issue(s, s * BK);
        asm volatile("cp.async.commit_group;" ::: "memory");
    }

    for (int ch = 0; ch < NCH; ch++) {
        asm volatile("cp.async.wait_group 2;" ::: "memory");
        __syncthreads();                 // stage (ch&3) arrived; prior reads done
        convertA(ch & 3);                // write single-buffer fp16 A planes
        __syncthreads();                 // converts visible to all warps
        int nx = ch + 3;
        if (nx < NCH) issue(nx & 3, nx * BK);   // overlap copy with MMAs below
        asm volatile("cp.async.commit_group;" ::: "memory");
        compute(ch & 3);
    }

    // epilogue: undo power-of-two B scale (exact); write split-K partial plane
    const float binv = g_binv;
    float* Cop = Cout + (size_t)z * N_ * F_;
#pragma unroll
    for (int mi = 0; mi < 4; mi++) {
#pragma unroll
        for (int ni = 0; ni < 4; ni++) {
            int row0 = n0 + wm + mi * 16 + g;
            int col  = o0 + wn + ni * 8 + t * 2;
            *(float2*)(Cop + (size_t)row0 * F_ + col) =
                make_float2(acc[mi][ni][0] * binv, acc[mi][ni][1] * binv);
            *(float2*)(Cop + (size_t)(row0 + 8) * F_ + col) =
                make_float2(acc[mi][ni][2] * binv, acc[mi][ni][3] * binv);
        }
    }
}

// ============================================================================
// reduce: H[n,o] = sum over 16 split-K partial planes (fixed order),
// plus hi/lo fp16 planes of H * 2^-4 (exact scale; for the layer-2 small GEMM)
// ============================================================================
__global__ void reduce_kernel(float* __restrict__ Hout)
{
    int idx = blockIdx.x * 256 + threadIdx.x;
    float s = 0.f;
#pragma unroll
    for (int z = 0; z < R_ * KSPLIT; z++)
        s += g_T2[(size_t)z * N_ * F_ + idx];
    Hout[idx] = s;
    float hs = s * 0.0625f;              // 2^-4, exact
    __half h, l;
    split_h(hs, h, l);
    g_Hh[idx] = h;
    g_Hl[idx] = l;
}

__global__ void diag_kernel(const float* __restrict__ M)
{
    int i = blockIdx.x * 256 + threadIdx.x;
    int r = i >> 8, f = i & 255;
    g_diag[i] = M[(size_t)r * F_ * F_ + (size_t)f * F_ + f];
}

__global__ void score_kernel(const int* __restrict__ e1, const int* __restrict__ rel,
                             const int* __restrict__ e2, float* __restrict__ out)
{
    int b = blockIdx.x * 8 + (threadIdx.x >> 5);
    int lane = threadIdx.x & 31;
    const float* p = g_H2 + (size_t)e1[b] * F_;
    const float* h = g_H2 + (size_t)e2[b] * F_;
    const float* m = g_diag + rel[b] * F_;
    float s = 0.f;
#pragma unroll
    for (int i = 0; i < 2; i++) {
        int off = (lane + i * 32) * 4;
        float4 pv = *(const float4*)(p + off);
        float4 hv = *(const float4*)(h + off);
        float4 mv = *(const float4*)(m + off);
        s += pv.x * mv.x * hv.x + pv.y * mv.y * hv.y
           + pv.z * mv.z * hv.z + pv.w * mv.w * hv.w;
    }
#pragma unroll
    for (int o = 16; o; o >>= 1) s += __shfl_xor_sync(0xffffffffu, s, o);
    if (lane == 0) out[b] = 1.f / (1.f + expf(-s));
}

// ============================================================================
extern "C" void kernel_launch(void* const* d_in, const int* in_sizes, int n_in,
                              void* d_out, int out_size)
{
    const float* A   = (const float*)d_in[0];  // [R,N,N]
    const float* X   = (const float*)d_in[1];  // [N,F]
    const float* c   = (const float*)d_in[2];  // [R,N,1]
    const float* W1  = (const float*)d_in[3];  // [R,F,F]
    const float* W2  = (const float*)d_in[4];  // [R,F,F]
    const float* M   = (const float*)d_in[5];  // [R,F,F] (diagonal)
    const int*   e1  = (const int*)d_in[6];
    const int*   rel = (const int*)d_in[7];
    const int*   e2  = (const int*)d_in[8];
    float* out = (float*)d_out;

    float *T1, *T2, *H1, *H2;
    __half *Xh, *Xl, *W1h, *W1l, *W2h, *W2l, *Hh, *Hl;
    cudaGetSymbolAddress((void**)&T1, g_T1);
    cudaGetSymbolAddress((void**)&T2, g_T2);
    cudaGetSymbolAddress((void**)&H1, g_H1);
    cudaGetSymbolAddress((void**)&H2, g_H2);
    cudaGetSymbolAddress((void**)&Xh, g_Xh);
    cudaGetSymbolAddress((void**)&Xl, g_Xl);
    cudaGetSymbolAddress((void**)&W1h, g_W1h);
    cudaGetSymbolAddress((void**)&W1l, g_W1l);
    cudaGetSymbolAddress((void**)&W2h, g_W2h);
    cudaGetSymbolAddress((void**)&W2l, g_W2l);
    cudaGetSymbolAddress((void**)&Hh, g_Hh);
    cudaGetSymbolAddress((void**)&Hl, g_Hl);

    cudaFuncSetAttribute(big_f16_kernel,
                         cudaFuncAttributeMaxDynamicSharedMemorySize, SMEM_BIG);
    cudaFuncSetAttribute(small_f16_kernel,
                         cudaFuncAttributeMaxDynamicSharedMemorySize, SMEM_SMALL);

    dim3 blk(256);
    dim3 grid_small(2, 32, 8);
    dim3 grid_big(2, 32, R_ * KSPLIT);   // 1024 tiles (split-K x2)
    dim3 grid_bsplit(N_ / 32, F_ / 32, 8), blk_bsplit(32, 8);

    // ---- input planes (once) ----
    presplit16_kernel<<<(N_ * F_) / 2048, blk>>>(X, Xh, Xl);
    presplit16_kernel<<<(R_ * F_ * F_) / 2048, blk>>>(W1, W1h, W1l);
    presplit16_kernel<<<(R_ * F_ * F_) / 2048, blk>>>(W2, W2h, W2l);

    // ---- layer 1: H1 = sum_r (c[r] o A[r]) @ (X @ W1[r]^T) ----
    reset_kernel<<<1, 1>>>();
    small_f16_kernel<<<grid_small, blk, SMEM_SMALL>>>(Xh, Xl, W1h, W1l, T1, 1.0f);
    finalize_kernel<<<1, 1>>>();
    bsplitB_kernel<<<grid_bsplit, blk_bsplit>>>(T1);
    big_f16_kernel<<<grid_big, blk, SMEM_BIG>>>(A, c, T2);
    reduce_kernel<<<(N_ * F_) / 256, blk>>>(H1);

    // ---- layer 2 (A-side = H1 planes scaled 2^-4; undone via unscale=16) ----
    reset_kernel<<<1, 1>>>();
    small_f16_kernel<<<grid_small, blk, SMEM_SMALL>>>(Hh, Hl, W2h, W2l, T1, 16.0f);
    finalize_kernel<<<1, 1>>>();
    bsplitB_kernel<<<grid_bsplit, blk_bsplit>>>(T1);
    big_f16_kernel<<<grid_big, blk, SMEM_BIG>>>(A, c, T2);
    reduce_kernel<<<(N_ * F_) / 256, blk>>>(H2);

    // ---- scoring: diag(M[rel]) three-way dot + sigmoid ----
    diag_kernel<<<(R_ * F_) / 256, blk>>>(M);
    score_kernel<<<B_ / 8, blk>>>(e1, rel, e2, out);
}

// round 15
// speedup vs baseline: 1.2710x; 1.2710x over previous
#include <cuda_runtime.h>
#include <cuda_fp16.h>
#include <math.h>
#include <stdint.h>

#define R_ 8
#define N_ 4096
#define F_ 256
#define B_ 16384
#define KSPLIT 2
#define KHALF (N_ / KSPLIT)         // 2048

// ---------------- scratch (device globals; no allocs allowed) ----------------
__device__ float g_T1[(size_t)R_ * N_ * F_];            // 32 MB
__device__ float g_T2[(size_t)R_ * KSPLIT * N_ * F_];   // 64 MB (split-K partials)
__device__ float g_H1[(size_t)N_ * F_];                 // 4 MB
__device__ float g_H2[(size_t)N_ * F_];                 // 4 MB
__device__ float g_diag[R_ * F_];
__device__ unsigned g_maxbits;
__device__ float g_bscale, g_binv;
// fp16 planes: A (c folded), computed ONCE, reused by both layers
__device__ __half g_Ah[(size_t)R_ * N_ * N_];  // 256 MB
__device__ __half g_Al[(size_t)R_ * N_ * N_];  // 256 MB
// fp16 planes: B = bscale * T1, transposed to [r][o][k]
__device__ __half g_Bh[(size_t)R_ * F_ * N_];  // 16 MB
__device__ __half g_Bl[(size_t)R_ * F_ * N_];  // 16 MB
// fp16 planes for the small GEMMs
__device__ __half g_Xh[(size_t)N_ * F_], g_Xl[(size_t)N_ * F_];        // features
__device__ __half g_W1h[(size_t)R_ * F_ * F_], g_W1l[(size_t)R_ * F_ * F_];
__device__ __half g_W2h[(size_t)R_ * F_ * F_], g_W2l[(size_t)R_ * F_ * F_];
__device__ __half g_Hh[(size_t)N_ * F_], g_Hl[(size_t)N_ * F_];        // H1 * 2^-4

// ---------------- mma / ldmatrix / cp.async helpers ----------------
__device__ __forceinline__ void mma_f16(float* d, const uint32_t* a, const uint32_t* b) {
    asm volatile(
        "mma.sync.aligned.m16n8k16.row.col.f32.f16.f16.f32 "
        "{%0,%1,%2,%3}, {%4,%5,%6,%7}, {%8,%9}, {%0,%1,%2,%3};"
        : "+f"(d[0]), "+f"(d[1]), "+f"(d[2]), "+f"(d[3])
        : "r"(a[0]), "r"(a[1]), "r"(a[2]), "r"(a[3]), "r"(b[0]), "r"(b[1]));
}
__device__ __forceinline__ void ldm4(uint32_t& r0, uint32_t& r1, uint32_t& r2, uint32_t& r3,
                                     uint32_t addr) {
    asm volatile("ldmatrix.sync.aligned.m8n8.x4.shared.b16 {%0,%1,%2,%3}, [%4];"
                 : "=r"(r0), "=r"(r1), "=r"(r2), "=r"(r3) : "r"(addr));
}
__device__ __forceinline__ void cpasync16(uint32_t dst, const void* src) {
    asm volatile("cp.async.ca.shared.global [%0], [%1], 16;" :: "r"(dst), "l"(src));
}
__device__ __forceinline__ uint32_t smem_u32(const void* p) {
    uint32_t a;
    asm("{ .reg .u64 t; cvta.to.shared.u64 t, %1; cvt.u32.u64 %0, t; }" : "=r"(a) : "l"(p));
    return a;
}
__device__ __forceinline__ void split_h(float x, __half& h, __half& l) {
    h = __float2half_rn(x);
    l = __float2half_rn(x - __half2float(h));
}

// ============================================================================
// presplit A: Ah/Al = split(c[r,n] * A[r,n,k]), layout unchanged [r][n][k]
// (R13-proven; restored after R14's in-kernel convert regressed)
// ============================================================================
__global__ __launch_bounds__(256)
void presplitA_kernel(const float* __restrict__ A, const float* __restrict__ c)
{
    size_t tgl = (size_t)blockIdx.x * 256 + threadIdx.x;
    size_t rn = tgl >> 9;
    int seg = (int)(tgl & 511);
    const float* src = A + rn * (size_t)N_ + seg * 8;
    float cv = __ldg(c + rn);
    float4 v0 = *(const float4*)src;
    float4 v1 = *(const float4*)(src + 4);
    float a[8] = {v0.x * cv, v0.y * cv, v0.z * cv, v0.w * cv,
                  v1.x * cv, v1.y * cv, v1.z * cv, v1.w * cv};
    __half h[8], l[8];
#pragma unroll
    for (int i = 0; i < 8; i++) split_h(a[i], h[i], l[i]);
    size_t off = rn * (size_t)N_ + seg * 8;
    *(uint4*)(g_Ah + off) = *(uint4*)h;
    *(uint4*)(g_Al + off) = *(uint4*)l;
}

// ============================================================================
// generic fp32 -> hi/lo fp16 plane split (8 elements/thread, no scale)
// ============================================================================
__global__ __launch_bounds__(256)
void presplit16_kernel(const float* __restrict__ src,
                       __half* __restrict__ dh, __half* __restrict__ dl)
{
    size_t i = ((size_t)blockIdx.x * 256 + threadIdx.x) * 8;
    float4 v0 = *(const float4*)(src + i);
    float4 v1 = *(const float4*)(src + i + 4);
    float a[8] = {v0.x, v0.y, v0.z, v0.w, v1.x, v1.y, v1.z, v1.w};
    __half h[8], l[8];
#pragma unroll
    for (int j = 0; j < 8; j++) split_h(a[j], h[j], l[j]);
    *(uint4*)(dh + i) = *(uint4*)h;
    *(uint4*)(dl + i) = *(uint4*)l;
}

// ============================================================================
// bsplit B: T1 [r][k][o] fp32 -> Bh/Bl [r][o][k] fp16 (transpose + scale + split)
// ============================================================================
__global__ void bsplitB_kernel(const float* __restrict__ T1)
{
    __shared__ float tile[32][33];
    const int tx = threadIdx.x, ty = threadIdx.y;   // (32, 8)
    const int k0 = blockIdx.x * 32, o0 = blockIdx.y * 32, r = blockIdx.z;
    const float s = g_bscale;

    const float* src = T1 + ((size_t)r * N_ + k0) * F_ + o0;
#pragma unroll
    for (int j = 0; j < 4; j++)
        tile[ty + j * 8][tx] = src[(size_t)(ty + j * 8) * F_ + tx];
    __syncthreads();

#pragma unroll
    for (int j = 0; j < 4; j++) {
        int o = ty + j * 8;
        float x = tile[tx][o] * s;
        __half h, l;
        split_h(x, h, l);
        size_t base = ((size_t)r * F_ + o0 + o) * (size_t)N_ + k0 + tx;
        g_Bh[base] = h;
        g_Bl[base] = l;
    }
}

__global__ void reset_kernel() { g_maxbits = 0u; }
__global__ void finalize_kernel() {
    float mx = __uint_as_float(g_maxbits);
    int ex = 0;
    frexpf(mx, &ex);
    int e = ex > 12 ? ex - 12 : 0;   // scaled max <= 4096
    g_bscale = exp2f((float)(-e));
    g_binv   = exp2f((float)(e));
}

// ============================================================================
// small fp16 MMA GEMM (3-product EFT): T1[r][n][o] = unscale * sum_k Ap[n,k]*Bp[r,o,k]
// K=256 (16 chunks). Verified rel_err 0.0 in R14.
// Epilogue: store fp32 + maxabs -> g_maxbits.
// ============================================================================
#define BK 16
#define S_NCH (F_ / BK)             // 16
#define STG_AH 0
#define STG_AL 6144
#define STG_BH 12288
#define STG_BL 18432
#define STG_BYTES 24576
#define SMEM_F16 (4 * STG_BYTES)    // 98304

__global__ __launch_bounds__(256, 2)
void small_f16_kernel(const __half* __restrict__ Aph, const __half* __restrict__ Apl,
                      const __half* __restrict__ Bph, const __half* __restrict__ Bpl,
                      float* __restrict__ Cout, float unscale)
{
    extern __shared__ __align__(16) char smc[];
    uint32_t sb = smem_u32(smc);

    const int tid = threadIdx.x;
    const int wid = tid >> 5;
    const int lane = tid & 31;
    const int g = lane >> 2;
    const int t = lane & 3;

    const int r  = blockIdx.z;
    const int n0 = blockIdx.y * 128;
    const int o0 = blockIdx.x * 128;
    const int wm = (wid & 1) * 64;
    const int wn = (wid >> 1) * 32;

    const int row = tid >> 1, half = tid & 1;
    const __half* sAh = Aph + (size_t)(n0 + row) * F_ + half * 8;   // shared across r
    const __half* sAl = Apl + (size_t)(n0 + row) * F_ + half * 8;
    const __half* sBh = Bph + ((size_t)(r * F_ + o0 + row)) * F_ + half * 8;
    const __half* sBl = Bpl + ((size_t)(r * F_ + o0 + row)) * F_ + half * 8;
    const uint32_t doff = (uint32_t)(row * 48 + half * 16);

    const uint32_t lma = (uint32_t)((wm + ((lane >> 3) & 1) * 8 + (lane & 7)) * 48
                                    + ((lane >> 4) & 1) * 16);
    const uint32_t lmb = (uint32_t)((wn + ((lane >> 4) & 1) * 8 + (lane & 7)) * 48
                                    + ((lane >> 3) & 1) * 16);

    float acc[4][4][4];
#pragma unroll
    for (int mi = 0; mi < 4; mi++)
#pragma unroll
        for (int ni = 0; ni < 4; ni++)
#pragma unroll
            for (int q = 0; q < 4; q++) acc[mi][ni][q] = 0.f;

    auto issue = [&](int stage, int k0) {
        uint32_t d = sb + stage * STG_BYTES + doff;
        cpasync16(d + STG_AH, sAh + k0);
        cpasync16(d + STG_AL, sAl + k0);
        cpasync16(d + STG_BH, sBh + k0);
        cpasync16(d + STG_BL, sBl + k0);
    };

    auto compute = [&](int stage) {
        uint32_t base = sb + stage * STG_BYTES;
        uint32_t bh[4][2], bl[4][2];
#pragma unroll
        for (int p = 0; p < 2; p++) {
            uint32_t r0, r1, r2, r3;
            ldm4(r0, r1, r2, r3, base + STG_BH + lmb + p * 768);
            bh[2 * p][0] = r0; bh[2 * p][1] = r1;
            bh[2 * p + 1][0] = r2; bh[2 * p + 1][1] = r3;
            ldm4(r0, r1, r2, r3, base + STG_BL + lmb + p * 768);
            bl[2 * p][0] = r0; bl[2 * p][1] = r1;
            bl[2 * p + 1][0] = r2; bl[2 * p + 1][1] = r3;
        }
#pragma unroll
        for (int mi = 0; mi < 4; mi++) {
            uint32_t ah[4], al[4];
            ldm4(ah[0], ah[1], ah[2], ah[3], base + STG_AH + lma + mi * 768);
            ldm4(al[0], al[1], al[2], al[3], base + STG_AL + lma + mi * 768);
#pragma unroll
            for (int ni = 0; ni < 4; ni++) {
                mma_f16(acc[mi][ni], ah, bh[ni]);
                mma_f16(acc[mi][ni], ah, bl[ni]);
                mma_f16(acc[mi][ni], al, bh[ni]);
            }
        }
    };

#pragma unroll
    for (int s = 0; s < 3; s++) {
        issue(s, s * BK);
        asm volatile("cp.async.commit_group;" ::: "memory");
    }
    for (int ch = 0; ch < S_NCH; ch++) {
        asm volatile("cp.async.wait_group 2;" ::: "memory");
        __syncthreads();
        compute(ch & 3);
        int nx = ch + 3;
        if (nx < S_NCH) issue(nx & 3, nx * BK);
        asm volatile("cp.async.commit_group;" ::: "memory");
    }

    // epilogue: unscale, store fp32 T1, maxabs reduction
    float mx = 0.f;
    float* Cop = Cout + (size_t)r * N_ * F_;
#pragma unroll
    for (int mi = 0; mi < 4; mi++) {
#pragma unroll
        for (int ni = 0; ni < 4; ni++) {
            int row0 = n0 + wm + mi * 16 + g;
            int col  = o0 + wn + ni * 8 + t * 2;
            float v0 = acc[mi][ni][0] * unscale, v1 = acc[mi][ni][1] * unscale;
            float v2 = acc[mi][ni][2] * unscale, v3 = acc[mi][ni][3] * unscale;
            *(float2*)(Cop + (size_t)row0 * F_ + col) = make_float2(v0, v1);
            *(float2*)(Cop + (size_t)(row0 + 8) * F_ + col) = make_float2(v2, v3);
            mx = fmaxf(mx, fmaxf(fmaxf(fabsf(v0), fabsf(v1)), fmaxf(fabsf(v2), fabsf(v3))));
        }
    }
#pragma unroll
    for (int o = 16; o; o >>= 1) mx = fmaxf(mx, __shfl_xor_sync(0xffffffffu, mx, o));
    if (lane == 0) atomicMax(&g_maxbits, __float_as_uint(mx));
}

// ============================================================================
// big fp16 MMA GEMM, SPLIT-K x2 — R13-proven version (reads presplit A planes)
// ============================================================================
#define NCH (KHALF / BK)            // 128 chunks per CTA
#define SMEM_BIG (4 * STG_BYTES)    // 98304

__global__ __launch_bounds__(256, 2)
void big_f16_kernel(float* __restrict__ Cout)
{
    extern __shared__ __align__(16) char smc[];
    uint32_t sb = smem_u32(smc);

    const int tid = threadIdx.x;
    const int wid = tid >> 5;
    const int lane = tid & 31;
    const int g = lane >> 2;
    const int t = lane & 3;

    const int z  = blockIdx.z;          // 0..15
    const int r  = z >> 1;
    const int kh = z & 1;
    const int kbase = kh * KHALF;
    const int n0 = blockIdx.y * 128;
    const int o0 = blockIdx.x * 128;
    const int wm = (wid & 1) * 64;
    const int wn = (wid >> 1) * 32;

    const int row = tid >> 1, half = tid & 1;
    const size_t aoffg = ((size_t)(r * N_ + n0 + row)) * N_ + kbase + half * 8;
    const size_t boffg = ((size_t)(r * F_ + o0 + row)) * N_ + kbase + half * 8;
    const __half* sAh = g_Ah + aoffg;
    const __half* sAl = g_Al + aoffg;
    const __half* sBh = g_Bh + boffg;
    const __half* sBl = g_Bl + boffg;
    const uint32_t doff = (uint32_t)(row * 48 + half * 16);

    const uint32_t lma = (uint32_t)((wm + ((lane >> 3) & 1) * 8 + (lane & 7)) * 48
                                    + ((lane >> 4) & 1) * 16);
    const uint32_t lmb = (uint32_t)((wn + ((lane >> 4) & 1) * 8 + (lane & 7)) * 48
                                    + ((lane >> 3) & 1) * 16);

    float acc[4][4][4];
#pragma unroll
    for (int mi = 0; mi < 4; mi++)
#pragma unroll
        for (int ni = 0; ni < 4; ni++)
#pragma unroll
            for (int q = 0; q < 4; q++) acc[mi][ni][q] = 0.f;

    auto issue = [&](int stage, int k0) {
        uint32_t d = sb + stage * STG_BYTES + doff;
        cpasync16(d + STG_AH, sAh + k0);
        cpasync16(d + STG_AL, sAl + k0);
        cpasync16(d + STG_BH, sBh + k0);
        cpasync16(d + STG_BL, sBl + k0);
    };

    auto compute = [&](int stage) {
        uint32_t base = sb + stage * STG_BYTES;
        uint32_t bh[4][2], bl[4][2];
#pragma unroll
        for (int p = 0; p < 2; p++) {
            uint32_t r0, r1, r2, r3;
            ldm4(r0, r1, r2, r3, base + STG_BH + lmb + p * 768);
            bh[2 * p][0] = r0; bh[2 * p][1] = r1;
            bh[2 * p + 1][0] = r2; bh[2 * p + 1][1] = r3;
            ldm4(r0, r1, r2, r3, base + STG_BL + lmb + p * 768);
            bl[2 * p][0] = r0; bl[2 * p][1] = r1;
            bl[2 * p + 1][0] = r2; bl[2 * p + 1][1] = r3;
        }
#pragma unroll
        for (int mi = 0; mi < 4; mi++) {
            uint32_t ah[4], al[4];
            ldm4(ah[0], ah[1], ah[2], ah[3], base + STG_AH + lma + mi * 768);
            ldm4(al[0], al[1], al[2], al[3], base + STG_AL + lma + mi * 768);
#pragma unroll
            for (int ni = 0; ni < 4; ni++) {
                mma_f16(acc[mi][ni], ah, bh[ni]);   // hi*hi
                mma_f16(acc[mi][ni], ah, bl[ni]);   // hi*lo
                mma_f16(acc[mi][ni], al, bh[ni]);   // lo*hi
            }
        }
    };

#pragma unroll
    for (int s = 0; s < 3; s++) {
        issue(s, s * BK);
        asm volatile("cp.async.commit_group;" ::: "memory");
    }

    for (int ch = 0; ch < NCH; ch++) {
        asm volatile("cp.async.wait_group 2;" ::: "memory");
        __syncthreads();
        compute(ch & 3);
        int nx = ch + 3;
        if (nx < NCH) issue(nx & 3, nx * BK);
        asm volatile("cp.async.commit_group;" ::: "memory");
    }

    // epilogue: undo power-of-two B scale (exact); write split-K partial plane
    const float binv = g_binv;
    float* Cop = Cout + (size_t)z * N_ * F_;
#pragma unroll
    for (int mi = 0; mi < 4; mi++) {
#pragma unroll
        for (int ni = 0; ni < 4; ni++) {
            int row0 = n0 + wm + mi * 16 + g;
            int col  = o0 + wn + ni * 8 + t * 2;
            *(float2*)(Cop + (size_t)row0 * F_ + col) =
                make_float2(acc[mi][ni][0] * binv, acc[mi][ni][1] * binv);
            *(float2*)(Cop + (size_t)(row0 + 8) * F_ + col) =
                make_float2(acc[mi][ni][2] * binv, acc[mi][ni][3] * binv);
        }
    }
}

// ============================================================================
// reduce: H[n,o] = sum over 16 split-K partial planes (fixed order),
// plus hi/lo fp16 planes of H * 2^-4 (exact scale; for layer-2 small GEMM)
// ============================================================================
__global__ void reduce_kernel(float* __restrict__ Hout)
{
    int idx = blockIdx.x * 256 + threadIdx.x;
    float s = 0.f;
#pragma unroll
    for (int z = 0; z < R_ * KSPLIT; z++)
        s += g_T2[(size_t)z * N_ * F_ + idx];
    Hout[idx] = s;
    float hs = s * 0.0625f;              // 2^-4, exact
    __half h, l;
    split_h(hs, h, l);
    g_Hh[idx] = h;
    g_Hl[idx] = l;
}

__global__ void diag_kernel(const float* __restrict__ M)
{
    int i = blockIdx.x * 256 + threadIdx.x;
    int r = i >> 8, f = i & 255;
    g_diag[i] = M[(size_t)r * F_ * F_ + (size_t)f * F_ + f];
}

__global__ void score_kernel(const int* __restrict__ e1, const int* __restrict__ rel,
                             const int* __restrict__ e2, float* __restrict__ out)
{
    int b = blockIdx.x * 8 + (threadIdx.x >> 5);
    int lane = threadIdx.x & 31;
    const float* p = g_H2 + (size_t)e1[b] * F_;
    const float* h = g_H2 + (size_t)e2[b] * F_;
    const float* m = g_diag + rel[b] * F_;
    float s = 0.f;
#pragma unroll
    for (int i = 0; i < 2; i++) {
        int off = (lane + i * 32) * 4;
        float4 pv = *(const float4*)(p + off);
        float4 hv = *(const float4*)(h + off);
        float4 mv = *(const float4*)(m + off);
        s += pv.x * mv.x * hv.x + pv.y * mv.y * hv.y
           + pv.z * mv.z * hv.z + pv.w * mv.w * hv.w;
    }
#pragma unroll
    for (int o = 16; o; o >>= 1) s += __shfl_xor_sync(0xffffffffu, s, o);
    if (lane == 0) out[b] = 1.f / (1.f + expf(-s));
}

// ============================================================================
extern "C" void kernel_launch(void* const* d_in, const int* in_sizes, int n_in,
                              void* d_out, int out_size)
{
    const float* A   = (const float*)d_in[0];  // [R,N,N]
    const float* X   = (const float*)d_in[1];  // [N,F]
    const float* c   = (const float*)d_in[2];  // [R,N,1]
    const float* W1  = (const float*)d_in[3];  // [R,F,F]
    const float* W2  = (const float*)d_in[4];  // [R,F,F]
    const float* M   = (const float*)d_in[5];  // [R,F,F] (diagonal)
    const int*   e1  = (const int*)d_in[6];
    const int*   rel = (const int*)d_in[7];
    const int*   e2  = (const int*)d_in[8];
    float* out = (float*)d_out;

    float *T1, *T2, *H1, *H2;
    __half *Xh, *Xl, *W1h, *W1l, *W2h, *W2l, *Hh, *Hl;
    cudaGetSymbolAddress((void**)&T1, g_T1);
    cudaGetSymbolAddress((void**)&T2, g_T2);
    cudaGetSymbolAddress((void**)&H1, g_H1);
    cudaGetSymbolAddress((void**)&H2, g_H2);
    cudaGetSymbolAddress((void**)&Xh, g_Xh);
    cudaGetSymbolAddress((void**)&Xl, g_Xl);
    cudaGetSymbolAddress((void**)&W1h, g_W1h);
    cudaGetSymbolAddress((void**)&W1l, g_W1l);
    cudaGetSymbolAddress((void**)&W2h, g_W2h);
    cudaGetSymbolAddress((void**)&W2l, g_W2l);
    cudaGetSymbolAddress((void**)&Hh, g_Hh);
    cudaGetSymbolAddress((void**)&Hl, g_Hl);

    cudaFuncSetAttribute(big_f16_kernel,
                         cudaFuncAttributeMaxDynamicSharedMemorySize, SMEM_BIG);
    cudaFuncSetAttribute(small_f16_kernel,
                         cudaFuncAttributeMaxDynamicSharedMemorySize, SMEM_F16);

    dim3 blk(256);
    dim3 grid_small(2, 32, 8);
    dim3 grid_big(2, 32, R_ * KSPLIT);   // 1024 tiles (split-K x2)
    dim3 grid_bsplit(N_ / 32, F_ / 32, 8), blk_bsplit(32, 8);

    // ---- input planes (once) ----
    presplitA_kernel<<<((size_t)R_ * N_ * N_ / 8) / 256, blk>>>(A, c);
    presplit16_kernel<<<(N_ * F_) / 2048, blk>>>(X, Xh, Xl);
    presplit16_kernel<<<(R_ * F_ * F_) / 2048, blk>>>(W1, W1h, W1l);
    presplit16_kernel<<<(R_ * F_ * F_) / 2048, blk>>>(W2, W2h, W2l);

    // ---- layer 1: H1 = sum_r (c[r] o A[r]) @ (X @ W1[r]^T) ----
    reset_kernel<<<1, 1>>>();
    small_f16_kernel<<<grid_small, blk, SMEM_F16>>>(Xh, Xl, W1h, W1l, T1, 1.0f);
    finalize_kernel<<<1, 1>>>();
    bsplitB_kernel<<<grid_bsplit, blk_bsplit>>>(T1);
    big_f16_kernel<<<grid_big, blk, SMEM_BIG>>>(T2);
    reduce_kernel<<<(N_ * F_) / 256, blk>>>(H1);

    // ---- layer 2 (A-side = H1 planes scaled 2^-4; undone via unscale=16) ----
    reset_kernel<<<1, 1>>>();
    small_f16_kernel<<<grid_small, blk, SMEM_F16>>>(Hh, Hl, W2h, W2l, T1, 16.0f);
    finalize_kernel<<<1, 1>>>();
    bsplitB_kernel<<<grid_bsplit, blk_bsplit>>>(T1);
    big_f16_kernel<<<grid_big, blk, SMEM_BIG>>>(T2);
    reduce_kernel<<<(N_ * F_) / 256, blk>>>(H2);

    // ---- scoring: diag(M[rel]) three-way dot + sigmoid ----
    diag_kernel<<<(R_ * F_) / 256, blk>>>(M);
    score_kernel<<<B_ / 8, blk>>>(e1, rel, e2, out);
}